// round 1
// baseline (speedup 1.0000x reference)
#include <cuda_runtime.h>
#include <cuda_bf16.h>
#include <math.h>

// ---------------- problem constants ----------------
#define B_   32
#define TW   40
#define N_   50
#define CIN  2
#define H_   128
#define CO_  64
#define E_   800
#define T1   38            // after tconv1
#define T2T  36            // after tconv2
#define T3   34            // after conv3
#define NG   (B_*T1)       // 1216 graphs
#define J_   (N_*CO_)      // 3200
#define OC3  128           // conv3 out channels

// ---------------- scratch (static device, no allocation) ----------------
__device__ float g_T0[NG*N_*H_];          // 7,782,400
__device__ float g_G [NG*N_*H_];          // 7,782,400
__device__ float g_T2[B_*T2T*N_*CO_];     // 3,686,400
__device__ float g_V [B_*3*J_];           // 307,200
__device__ float g_scale[N_], g_shift[N_];
__device__ float g_pooled[B_*OC3];

// ============================================================
// K1: tconv1  X(B,40,50,2) -> T0(B,38,50,128), relu(P*sig(Q)+R)
// one block per (b,n), 128 threads over h
// ============================================================
__global__ void k_tconv1(const float* __restrict__ X,
                         const float* __restrict__ w1, const float* __restrict__ b1,
                         const float* __restrict__ w2, const float* __restrict__ b2,
                         const float* __restrict__ w3, const float* __restrict__ b3)
{
    int bn = blockIdx.x;
    int b = bn / N_, n = bn % N_;
    int h = threadIdx.x;

    __shared__ float xs[TW*CIN];
    for (int i = threadIdx.x; i < TW*CIN; i += blockDim.x) {
        int t = i >> 1, c = i & 1;
        xs[i] = X[((b*TW + t)*N_ + n)*CIN + c];
    }
    float W1[6], W2[6], W3[6];
#pragma unroll
    for (int q = 0; q < 6; q++) {
        W1[q] = w1[q*H_ + h]; W2[q] = w2[q*H_ + h]; W3[q] = w3[q*H_ + h];
    }
    float B1 = b1[h], B2 = b2[h], B3 = b3[h];
    __syncthreads();

    for (int t = 0; t < T1; t++) {
        float P = B1, Q = B2, R = B3;
#pragma unroll
        for (int k = 0; k < 3; k++)
#pragma unroll
            for (int c = 0; c < 2; c++) {
                float v = xs[(t+k)*2 + c];
                int q = k*2 + c;
                P += v*W1[q]; Q += v*W2[q]; R += v*W3[q];
            }
        float s = 1.f/(1.f + expf(-Q));
        float o = P*s + R;
        o = o > 0.f ? o : 0.f;
        g_T0[((size_t)(b*T1 + t)*N_ + n)*H_ + h] = o;
    }
}

// ============================================================
// K2: Chebyshev conv per graph.  One block per graph g=b*38+t.
// Build dense A (50x50) in smem, 2 dense props, fused 50x128x384 GEMM.
// dyn smem layout (floats): A[2500] | x0[7168] | t1[7168] | t2[7168] | dis[64] | deg[64]
// ============================================================
#define CH_PAD 7168   // 56 rows * 128
__global__ void k_cheb(const int* __restrict__ EI,
                       const float* __restrict__ W,   // (3,128,128)
                       const float* __restrict__ bias)
{
    extern __shared__ float sm[];
    float* A   = sm;
    float* x0  = sm + 2500;
    float* t1  = x0 + CH_PAD;
    float* t2  = t1 + CH_PAD;
    float* dis = t2 + CH_PAD;
    int*   deg = (int*)(dis + 64);

    int g = blockIdx.x;
    int b = g / T1, t = g % T1;
    int tid = threadIdx.x;               // 256

    for (int i = tid; i < 2500; i += 256) A[i] = 0.f;
    if (tid < N_) deg[tid] = 0;
    __syncthreads();

    const int* rows = EI + ((size_t)(b*TW + t)*2 + 0)*E_;
    const int* cols = EI + ((size_t)(b*TW + t)*2 + 1)*E_;
    for (int e = tid; e < E_; e += 256) atomicAdd(&deg[rows[e]], 1);
    __syncthreads();
    if (tid < N_) { int d = deg[tid]; dis[tid] = d > 0 ? rsqrtf((float)d) : 0.f; }
    __syncthreads();
    for (int e = tid; e < E_; e += 256) {
        int r = rows[e], c = cols[e];
        atomicAdd(&A[r*N_ + c], -dis[r]*dis[c]);
    }

    // load x0 = T0[g]  (50x128)
    {
        const float4* src = (const float4*)(g_T0 + (size_t)g*N_*H_);
        float4* dst = (float4*)x0;
        for (int i = tid; i < N_*H_/4; i += 256) dst[i] = src[i];
    }
    __syncthreads();

    int tx = tid & 31;     // float4 column group within 128
    int ng = tid >> 5;     // 0..7

    // t1 = A @ x0
#pragma unroll
    for (int i = 0; i < 7; i++) {
        int n = ng + 8*i;
        if (n < N_) {
            float4 acc = make_float4(0,0,0,0);
            const float* Ar = A + n*N_;
            for (int m = 0; m < N_; m++) {
                float a = Ar[m];
                float4 xv = ((const float4*)(x0 + m*H_))[tx];
                acc.x += a*xv.x; acc.y += a*xv.y; acc.z += a*xv.z; acc.w += a*xv.w;
            }
            ((float4*)(t1 + n*H_))[tx] = acc;
        }
    }
    __syncthreads();

    // t2 = 2*A@t1 - x0
#pragma unroll
    for (int i = 0; i < 7; i++) {
        int n = ng + 8*i;
        if (n < N_) {
            float4 acc = make_float4(0,0,0,0);
            const float* Ar = A + n*N_;
            for (int m = 0; m < N_; m++) {
                float a = Ar[m];
                float4 xv = ((const float4*)(t1 + m*H_))[tx];
                acc.x += a*xv.x; acc.y += a*xv.y; acc.z += a*xv.z; acc.w += a*xv.w;
            }
            float4 xo = ((const float4*)(x0 + n*H_))[tx];
            acc.x = 2.f*acc.x - xo.x; acc.y = 2.f*acc.y - xo.y;
            acc.z = 2.f*acc.z - xo.z; acc.w = 2.f*acc.w - xo.w;
            ((float4*)(t2 + n*H_))[tx] = acc;
        }
    }
    __syncthreads();

    // GEMM: G[n][o] = relu( sum_k sum_f Tk[n][f] * W[k][f][o] + bias[o] )
    int ty = tid >> 5;     // warp id -> row group
    float acc[7][4];
#pragma unroll
    for (int i = 0; i < 7; i++)
#pragma unroll
        for (int j = 0; j < 4; j++) acc[i][j] = 0.f;

    const float* bases[3] = { x0, t1, t2 };
#pragma unroll
    for (int kk = 0; kk < 3; kk++) {
        const float* Tb = bases[kk];
        const float* Wb = W + kk*H_*H_ + tx*4;
        for (int f = 0; f < H_; f++) {
            float4 wv = *(const float4*)(Wb + f*H_);
#pragma unroll
            for (int i = 0; i < 7; i++) {
                float a = Tb[(ty + 8*i)*H_ + f];   // padded rows -> in-bounds
                acc[i][0] += a*wv.x; acc[i][1] += a*wv.y;
                acc[i][2] += a*wv.z; acc[i][3] += a*wv.w;
            }
        }
    }
    float4 bv = *(const float4*)(bias + tx*4);
#pragma unroll
    for (int i = 0; i < 7; i++) {
        int n = ty + 8*i;
        if (n < N_) {
            float4 o;
            o.x = acc[i][0] + bv.x; o.y = acc[i][1] + bv.y;
            o.z = acc[i][2] + bv.z; o.w = acc[i][3] + bv.w;
            o.x = o.x > 0.f ? o.x : 0.f; o.y = o.y > 0.f ? o.y : 0.f;
            o.z = o.z > 0.f ? o.z : 0.f; o.w = o.w > 0.f ? o.w : 0.f;
            *(float4*)(g_G + ((size_t)g*N_ + n)*H_ + tx*4) = o;
        }
    }
}

// ============================================================
// K3: tconv2  G(B,38,50,128) -> T2(B,36,50,64), relu(P*sig(Q)+R)
// one block per (b,n), 256 threads
// ============================================================
__global__ void k_tconv2(const float* __restrict__ w1, const float* __restrict__ b1,
                         const float* __restrict__ w2, const float* __restrict__ b2,
                         const float* __restrict__ w3, const float* __restrict__ b3)
{
    __shared__ float xs[42*H_];   // 38 real rows + padding
    int bn = blockIdx.x;
    int b = bn / N_, n = bn % N_;
    int tid = threadIdx.x;

    for (int i = tid; i < T1*(H_/4); i += 256) {
        int t = i >> 5, q = i & 31;
        ((float4*)(xs + t*H_))[q] =
            *(const float4*)(g_G + ((size_t)(b*T1 + t)*N_ + n)*H_ + q*4);
    }
    __syncthreads();

    int ty = tid >> 5;           // 0..7 -> t rows ty+8i
    int tx = tid & 31;           // co pair = tx*2
    float2 P[5], Q[5], R[5];
#pragma unroll
    for (int i = 0; i < 5; i++) { P[i] = make_float2(0,0); Q[i] = make_float2(0,0); R[i] = make_float2(0,0); }

#pragma unroll
    for (int k = 0; k < 3; k++) {
        const float* W1 = w1 + (size_t)k*H_*CO_ + tx*2;
        const float* W2 = w2 + (size_t)k*H_*CO_ + tx*2;
        const float* W3 = w3 + (size_t)k*H_*CO_ + tx*2;
        for (int c = 0; c < H_; c++) {
            float2 v1 = *(const float2*)(W1 + c*CO_);
            float2 v2 = *(const float2*)(W2 + c*CO_);
            float2 v3 = *(const float2*)(W3 + c*CO_);
#pragma unroll
            for (int i = 0; i < 5; i++) {
                float a = xs[(ty + 8*i + k)*H_ + c];
                P[i].x += a*v1.x; P[i].y += a*v1.y;
                Q[i].x += a*v2.x; Q[i].y += a*v2.y;
                R[i].x += a*v3.x; R[i].y += a*v3.y;
            }
        }
    }
    float B1x = b1[tx*2], B1y = b1[tx*2+1];
    float B2x = b2[tx*2], B2y = b2[tx*2+1];
    float B3x = b3[tx*2], B3y = b3[tx*2+1];
#pragma unroll
    for (int i = 0; i < 5; i++) {
        int t = ty + 8*i;
        if (t < T2T) {
            float sx = 1.f/(1.f + expf(-(Q[i].x + B2x)));
            float sy = 1.f/(1.f + expf(-(Q[i].y + B2y)));
            float ox = (P[i].x + B1x)*sx + R[i].x + B3x;
            float oy = (P[i].y + B1y)*sy + R[i].y + B3y;
            ox = ox > 0.f ? ox : 0.f; oy = oy > 0.f ? oy : 0.f;
            *(float2*)(g_T2 + ((size_t)(b*T2T + t)*N_ + n)*CO_ + tx*2) = make_float2(ox, oy);
        }
    }
}

// ============================================================
// K4: BatchNorm stats per node n  (mean/var over B*36*64 = 73728)
// ============================================================
__global__ void k_bnstats(const float* __restrict__ gamma, const float* __restrict__ beta)
{
    int n = blockIdx.x;
    int tid = threadIdx.x;
    float s = 0.f, s2 = 0.f;
    const int TOT = B_*T2T*CO_;
    for (int i = tid; i < TOT; i += 256) {
        int row = i >> 6, co = i & 63;          // row = b*36+t
        float v = g_T2[((size_t)row*N_ + n)*CO_ + co];
        s += v; s2 += v*v;
    }
    __shared__ float red[512];
    red[tid] = s; red[256 + tid] = s2;
    __syncthreads();
    for (int st = 128; st > 0; st >>= 1) {
        if (tid < st) { red[tid] += red[tid+st]; red[256+tid] += red[256+tid+st]; }
        __syncthreads();
    }
    if (tid == 0) {
        float mean = red[0] / (float)TOT;
        float var  = red[256] / (float)TOT - mean*mean;
        float rstd = rsqrtf(var + 1e-5f);
        float sc = gamma[n]*rstd;
        g_scale[n] = sc;
        g_shift[n] = beta[n] - mean*sc;
    }
}

// ============================================================
// K5: build V[b][k][j]  (BN applied; conv3+mean-pool collapsed)
// V_k[b,j] = sum_{t'=k..33+k} Tr[b,t',j]
// ============================================================
__global__ void k_vprep()
{
    int b = blockIdx.x;
    int j = blockIdx.y*256 + threadIdx.x;
    if (j >= J_) return;
    int n = j / CO_;
    float sc = g_scale[n], sh = g_shift[n];
    const float* base = g_T2 + (size_t)b*T2T*J_ + j;
    float TS = 0.f, v0 = 0.f, v1 = 0.f, v34 = 0.f, v35 = 0.f;
    for (int t = 0; t < T2T; t++) {
        float x = base[(size_t)t*J_]*sc + sh;
        TS += x;
        if (t == 0)  v0 = x;
        if (t == 1)  v1 = x;
        if (t == 34) v34 = x;
        if (t == 35) v35 = x;
    }
    g_V[((size_t)b*3 + 0)*J_ + j] = TS - v34 - v35;
    g_V[((size_t)b*3 + 1)*J_ + j] = TS - v0  - v35;
    g_V[((size_t)b*3 + 2)*J_ + j] = TS - v0  - v1;
}

// ============================================================
// K6: pooled[b,o] = c3b[o] + (1/34) * dot(conv3_w[o,:,:], V[b,:,:])  (K=9600)
// ============================================================
__global__ void k_pooled(const float* __restrict__ c3w, const float* __restrict__ c3b)
{
    int o = blockIdx.x;
    int b = blockIdx.y;
    int tid = threadIdx.x;
    const float* w = c3w + (size_t)o*3*J_;
    const float* v = g_V + (size_t)b*3*J_;
    float s = 0.f;
    for (int i = tid; i < 3*J_; i += 256) s += w[i]*v[i];
    __shared__ float red[256];
    red[tid] = s; __syncthreads();
    for (int st = 128; st > 0; st >>= 1) {
        if (tid < st) red[tid] += red[tid+st];
        __syncthreads();
    }
    if (tid == 0) g_pooled[b*OC3 + o] = c3b[o] + red[0]*(1.f/34.f);
}

// ============================================================
// K7: out[b,j] = f1_b[j] + sum_o pooled[b,o]*f1_w[o,j]
// ============================================================
__global__ void k_fc(const float* __restrict__ f1w, const float* __restrict__ f1b,
                     float* __restrict__ out)
{
    int b = blockIdx.y;
    int j = blockIdx.x*128 + threadIdx.x;
    __shared__ float ps[OC3];
    ps[threadIdx.x] = g_pooled[b*OC3 + threadIdx.x];
    __syncthreads();
    float s = f1b[j];
#pragma unroll 4
    for (int o = 0; o < OC3; o++) s += ps[o]*f1w[(size_t)o*J_ + j];
    out[(size_t)b*J_ + j] = s;
}

// ============================================================
// host launcher
// ============================================================
extern "C" void kernel_launch(void* const* d_in, const int* in_sizes, int n_in,
                              void* d_out, int out_size)
{
    // classify inputs by element count (robust to dict-vs-signature ordering;
    // same-size groups have identical relative order in both)
    const float *X=0,*w11=0,*b11=0,*w12=0,*b12=0,*w13=0,*b13=0;
    const float *chw=0,*chb=0;
    const float *w21=0,*b21=0,*w22=0,*b22=0,*w23=0,*b23=0;
    const float *gamma=0,*beta=0,*c3w=0,*c3b=0,*f1w=0,*f1b=0;
    const int *ei=0;
    int c768=0, c128=0, c24576=0, c64=0, c50=0;
    for (int i = 0; i < n_in; i++) {
        int s = in_sizes[i];
        const void* p = d_in[i];
        switch (s) {
            case 128000:  X = (const float*)p; break;
            case 2048000: ei = (const int*)p; break;
            case 768:
                if (c768==0) w11=(const float*)p; else if (c768==1) w12=(const float*)p; else w13=(const float*)p;
                c768++; break;
            case 128:
                if (c128==0) b11=(const float*)p; else if (c128==1) b12=(const float*)p;
                else if (c128==2) b13=(const float*)p; else if (c128==3) chb=(const float*)p;
                else c3b=(const float*)p;
                c128++; break;
            case 49152:   chw = (const float*)p; break;
            case 24576:
                if (c24576==0) w21=(const float*)p; else if (c24576==1) w22=(const float*)p; else w23=(const float*)p;
                c24576++; break;
            case 64:
                if (c64==0) b21=(const float*)p; else if (c64==1) b22=(const float*)p; else b23=(const float*)p;
                c64++; break;
            case 50:
                if (c50==0) gamma=(const float*)p; else beta=(const float*)p;
                c50++; break;
            case 1228800: c3w = (const float*)p; break;
            case 409600:  f1w = (const float*)p; break;
            case 3200:    f1b = (const float*)p; break;
            default: break;
        }
    }
    float* out = (float*)d_out;

    // K2 needs 96,528 B dynamic smem
    static const int CH_SMEM = (2500 + 3*CH_PAD + 128) * 4;
    cudaFuncSetAttribute(k_cheb, cudaFuncAttributeMaxDynamicSharedMemorySize, CH_SMEM);

    k_tconv1<<<B_*N_, 128>>>(X, w11, b11, w12, b12, w13, b13);
    k_cheb  <<<NG, 256, CH_SMEM>>>(ei, chw, chb);
    k_tconv2<<<B_*N_, 256>>>(w21, b21, w22, b22, w23, b23);
    k_bnstats<<<N_, 256>>>(gamma, beta);
    k_vprep <<<dim3(B_, (J_+255)/256), 256>>>();
    k_pooled<<<dim3(OC3, B_), 256>>>(c3w, c3b);
    k_fc    <<<dim3(J_/128, B_), 128>>>(f1w, f1b, out);
}

// round 4
// speedup vs baseline: 2.1263x; 2.1263x over previous
#include <cuda_runtime.h>
#include <cuda_bf16.h>
#include <math.h>
#include <stdint.h>

// ---------------- problem constants ----------------
#define B_   32
#define TW   40
#define N_   50
#define CIN  2
#define H_   128
#define CO_  64
#define E_   800
#define T1   38            // after tconv1
#define T2T  36            // after tconv2
#define NG   (B_*T1)       // 1216 graphs
#define J_   (N_*CO_)      // 3200
#define OC3  128           // conv3 out channels
#define M_CH (NG*N_)       // 60800 rows, cheb GEMM
#define M_TC (B_*T2T*N_)   // 57600 rows, tconv2 GEMM

// ---------------- scratch (static device, no allocation) ----------------
__device__ float g_T0[NG*N_*H_];            // 7.78M
__device__ float g_TX[NG*3*N_*H_];          // 23.3M  [g][k][n][f]
__device__ float g_G [NG*N_*H_];            // 7.78M
__device__ float g_Wt2[384*192];            // packed tconv2 weights
__device__ float g_gate[(size_t)M_TC*192];  // 11.06M
__device__ float g_T2[(size_t)M_TC*CO_];    // 3.69M
__device__ float g_V [B_*3*J_];
__device__ float g_bnpart[N_*16*2];
__device__ float g_scale[N_], g_shift[N_];
__device__ float g_pooled[B_*OC3];

// ---------------- tf32 helpers ----------------
__device__ __forceinline__ uint32_t f2tf(float f) {
    uint32_t u; asm("cvt.rna.tf32.f32 %0, %1;" : "=r"(u) : "f"(f)); return u;
}
__device__ __forceinline__ uint4 cvt4(float4 v) {
    uint4 u; u.x = f2tf(v.x); u.y = f2tf(v.y); u.z = f2tf(v.z); u.w = f2tf(v.w);
    return u;
}
__device__ __forceinline__ void mma_tf32(float* c, const uint32_t* a, const uint32_t* b) {
    asm volatile("mma.sync.aligned.m16n8k8.row.col.f32.tf32.tf32.f32 "
        "{%0,%1,%2,%3}, {%4,%5,%6,%7}, {%8,%9}, {%0,%1,%2,%3};"
        : "+f"(c[0]), "+f"(c[1]), "+f"(c[2]), "+f"(c[3])
        : "r"(a[0]), "r"(a[1]), "r"(a[2]), "r"(a[3]), "r"(b[0]), "r"(b[1]));
}

// ============================================================
// K1: tconv1  X(B,40,50,2) -> T0(B,38,50,128)
// ============================================================
__global__ void k_tconv1(const float* __restrict__ X,
                         const float* __restrict__ w1, const float* __restrict__ b1,
                         const float* __restrict__ w2, const float* __restrict__ b2,
                         const float* __restrict__ w3, const float* __restrict__ b3)
{
    int bn = blockIdx.x;
    int b = bn / N_, n = bn % N_;
    int h = threadIdx.x;

    __shared__ float xs[TW*CIN];
    for (int i = threadIdx.x; i < TW*CIN; i += blockDim.x) {
        int t = i >> 1, c = i & 1;
        xs[i] = X[((b*TW + t)*N_ + n)*CIN + c];
    }
    float W1[6], W2[6], W3[6];
#pragma unroll
    for (int q = 0; q < 6; q++) {
        W1[q] = w1[q*H_ + h]; W2[q] = w2[q*H_ + h]; W3[q] = w3[q*H_ + h];
    }
    float B1 = b1[h], B2 = b2[h], B3 = b3[h];
    __syncthreads();

    for (int t = 0; t < T1; t++) {
        float P = B1, Q = B2, R = B3;
#pragma unroll
        for (int k = 0; k < 3; k++)
#pragma unroll
            for (int c = 0; c < 2; c++) {
                float v = xs[(t+k)*2 + c];
                int q = k*2 + c;
                P += v*W1[q]; Q += v*W2[q]; R += v*W3[q];
            }
        float s = 1.f/(1.f + expf(-Q));
        float o = P*s + R;
        o = o > 0.f ? o : 0.f;
        g_T0[((size_t)(b*T1 + t)*N_ + n)*H_ + h] = o;
    }
}

// ============================================================
// K2: Chebyshev propagation per graph -> g_TX[g][k][n][f]
// dyn smem floats: A[2500] | x0[6400] | t1[6400] | dis[64] | deg[64]
// ============================================================
__global__ void k_cheb_prop(const int* __restrict__ EI)
{
    extern __shared__ float sm[];
    float* A   = sm;
    float* x0  = sm + 2500;
    float* t1  = x0 + 6400;
    float* dis = t1 + 6400;
    int*   deg = (int*)(dis + 64);

    int g = blockIdx.x;
    int b = g / T1, t = g % T1;
    int tid = threadIdx.x;               // 256

    for (int i = tid; i < 2500; i += 256) A[i] = 0.f;
    if (tid < N_) deg[tid] = 0;
    __syncthreads();

    const int* rows = EI + ((size_t)(b*TW + t)*2 + 0)*E_;
    const int* cols = EI + ((size_t)(b*TW + t)*2 + 1)*E_;
    for (int e = tid; e < E_; e += 256) atomicAdd(&deg[rows[e]], 1);
    __syncthreads();
    if (tid < N_) { int d = deg[tid]; dis[tid] = d > 0 ? rsqrtf((float)d) : 0.f; }
    __syncthreads();
    for (int e = tid; e < E_; e += 256) {
        int r = rows[e], c = cols[e];
        atomicAdd(&A[r*N_ + c], -dis[r]*dis[c]);
    }

    // load x0 = T0[g] (50x128) -> smem, and copy to g_TX[g][0]
    {
        const float4* src = (const float4*)(g_T0 + (size_t)g*N_*H_);
        float4* dst = (float4*)x0;
        float4* dg  = (float4*)(g_TX + (size_t)g*3*N_*H_);
        for (int i = tid; i < N_*H_/4; i += 256) { float4 v = src[i]; dst[i] = v; dg[i] = v; }
    }
    __syncthreads();

    int tx = tid & 31;     // float4 column group
    int ng = tid >> 5;     // 0..7

    // t1 = A @ x0 -> smem + g_TX[g][1]
#pragma unroll
    for (int i = 0; i < 7; i++) {
        int n = ng + 8*i;
        if (n < N_) {
            float4 acc = make_float4(0,0,0,0);
            const float* Ar = A + n*N_;
            for (int m = 0; m < N_; m++) {
                float a = Ar[m];
                float4 xv = ((const float4*)(x0 + m*H_))[tx];
                acc.x += a*xv.x; acc.y += a*xv.y; acc.z += a*xv.z; acc.w += a*xv.w;
            }
            ((float4*)(t1 + n*H_))[tx] = acc;
            ((float4*)(g_TX + (size_t)g*3*N_*H_ + N_*H_ + n*H_))[tx] = acc;
        }
    }
    __syncthreads();

    // t2 = 2*A@t1 - x0 -> g_TX[g][2]
#pragma unroll
    for (int i = 0; i < 7; i++) {
        int n = ng + 8*i;
        if (n < N_) {
            float4 acc = make_float4(0,0,0,0);
            const float* Ar = A + n*N_;
            for (int m = 0; m < N_; m++) {
                float a = Ar[m];
                float4 xv = ((const float4*)(t1 + m*H_))[tx];
                acc.x += a*xv.x; acc.y += a*xv.y; acc.z += a*xv.z; acc.w += a*xv.w;
            }
            float4 xo = ((const float4*)(x0 + n*H_))[tx];
            acc.x = 2.f*acc.x - xo.x; acc.y = 2.f*acc.y - xo.y;
            acc.z = 2.f*acc.z - xo.z; acc.w = 2.f*acc.w - xo.w;
            ((float4*)(g_TX + (size_t)g*3*N_*H_ + 2*N_*H_ + n*H_))[tx] = acc;
        }
    }
}

// ============================================================
// K3: pack tconv2 weights: g_Wt2[kt*192 + gate*64 + co]
// ============================================================
__global__ void k_prepW(const float* __restrict__ w1, const float* __restrict__ w2,
                        const float* __restrict__ w3)
{
    int i = blockIdx.x*256 + threadIdx.x;   // over 384*64
    if (i < 384*64) {
        int kt = i >> 6, co = i & 63;
        g_Wt2[kt*192 + co]       = w1[i];
        g_Wt2[kt*192 + 64 + co]  = w2[i];
        g_Wt2[kt*192 + 128 + co] = w3[i];
    }
}

// ============================================================
// K4: tf32 MMA GEMM.  BM=128, BN=64, BK=32, 256 threads (8 warps 4x2)
// MODE 0: cheb  A=g_TX (M_CH x 384), B=cheb_w (384x128), bias+relu -> g_G
// MODE 1: tconv2 A=rows of g_G over kernel taps (M_TC x 384),
//         B=g_Wt2 (384x192), raw -> g_gate
// ============================================================
#define AST 36
#define BST 72
template<int MODE>
__global__ __launch_bounds__(256) void k_gemm(const float* __restrict__ Bext,
                                              const float* __restrict__ bias)
{
    __shared__ uint32_t As[128][AST];
    __shared__ uint32_t Bs[32][BST];

    const int tid  = threadIdx.x;
    const int bm   = blockIdx.x;
    const int nb   = blockIdx.y * 64;
    const int warp = tid >> 5, lane = tid & 31;
    const int wm = (warp & 3) * 32, wn = (warp >> 2) * 32;
    const int g4 = lane >> 2, tg = lane & 3;

    const int BNS = (MODE == 0) ? 128 : 192;
    const float* Bmat = (MODE == 0) ? Bext : g_Wt2;   // <-- R1 bug fix

    // per-thread fixed A-load coordinates
    const int arow = tid >> 3, ac4 = (tid & 7) << 2;
    const int brow = tid >> 4, bc4 = (tid & 15) << 2;

    size_t abase[4];
#pragma unroll
    for (int j = 0; j < 4; j++) {
        int R = bm*128 + arow + j*32;
        if (MODE == 0) {
            int g = R / N_, n = R - g*N_;
            abase[j] = (size_t)g*(3*N_*H_) + (size_t)n*H_;
        } else {
            int b = R / (T2T*N_);
            int rem = R - b*(T2T*N_);
            int t = rem / N_, n = rem - t*N_;
            abase[j] = ((size_t)(b*T1 + t)*N_ + n)*H_;
        }
    }
    const float* Abuf = (MODE == 0) ? g_TX : g_G;

    float acc[2][4][4];
#pragma unroll
    for (int mt = 0; mt < 2; mt++)
#pragma unroll
        for (int nt = 0; nt < 4; nt++)
#pragma unroll
            for (int q = 0; q < 4; q++) acc[mt][nt][q] = 0.f;

    for (int k0 = 0; k0 < 384; k0 += 32) {
        const int kk = k0 >> 7, fb = k0 & 127;
        // MODE 0: advance to chebyshev order kk (stride N_*H_ in g_TX)
        // MODE 1: advance to temporal tap kk (also stride N_*H_ in g_G)
        const size_t koff = (size_t)kk*(N_*H_) + fb;
#pragma unroll
        for (int j = 0; j < 4; j++) {
            float4 v = *(const float4*)(Abuf + abase[j] + koff + ac4);
            *(uint4*)&As[arow + j*32][ac4] = cvt4(v);
        }
#pragma unroll
        for (int j = 0; j < 2; j++) {
            int row = brow + j*16;
            float4 v = *(const float4*)(Bmat + (size_t)(k0 + row)*BNS + nb + bc4);
            *(uint4*)&Bs[row][bc4] = cvt4(v);
        }
        __syncthreads();
#pragma unroll
        for (int kt = 0; kt < 32; kt += 8) {
            uint32_t af[2][4], bf[4][2];
#pragma unroll
            for (int mt = 0; mt < 2; mt++) {
                int m = wm + mt*16;
                af[mt][0] = As[m + g4    ][kt + tg];
                af[mt][1] = As[m + g4 + 8][kt + tg];
                af[mt][2] = As[m + g4    ][kt + tg + 4];
                af[mt][3] = As[m + g4 + 8][kt + tg + 4];
            }
#pragma unroll
            for (int nt = 0; nt < 4; nt++) {
                bf[nt][0] = Bs[kt + tg    ][wn + nt*8 + g4];
                bf[nt][1] = Bs[kt + tg + 4][wn + nt*8 + g4];
            }
#pragma unroll
            for (int mt = 0; mt < 2; mt++)
#pragma unroll
                for (int nt = 0; nt < 4; nt++)
                    mma_tf32(acc[mt][nt], af[mt], bf[nt]);
        }
        __syncthreads();
    }

    // epilogue
#pragma unroll
    for (int mt = 0; mt < 2; mt++) {
        int r0 = bm*128 + wm + mt*16 + g4;
#pragma unroll
        for (int nt = 0; nt < 4; nt++) {
            int c = nb + wn + nt*8 + tg*2;
            float v0 = acc[mt][nt][0], v1 = acc[mt][nt][1];
            float v2 = acc[mt][nt][2], v3 = acc[mt][nt][3];
            if (MODE == 0) {
                float bx = bias[c], by = bias[c+1];
                v0 += bx; v1 += by; v2 += bx; v3 += by;
                v0 = v0 > 0.f ? v0 : 0.f; v1 = v1 > 0.f ? v1 : 0.f;
                v2 = v2 > 0.f ? v2 : 0.f; v3 = v3 > 0.f ? v3 : 0.f;
                *(float2*)(g_G + (size_t)r0*128 + c)      = make_float2(v0, v1);
                *(float2*)(g_G + (size_t)(r0+8)*128 + c)  = make_float2(v2, v3);
            } else {
                *(float2*)(g_gate + (size_t)r0*192 + c)     = make_float2(v0, v1);
                *(float2*)(g_gate + (size_t)(r0+8)*192 + c) = make_float2(v2, v3);
            }
        }
    }
}

// ============================================================
// K5: tconv2 gate epilogue: relu(P*sig(Q)+R) -> g_T2
// ============================================================
__global__ void k_tc2epi(const float* __restrict__ b1, const float* __restrict__ b2,
                         const float* __restrict__ b3)
{
    int idx = blockIdx.x*256 + threadIdx.x;      // over M_TC*64
    if (idx >= M_TC*CO_) return;
    int row = idx >> 6, co = idx & 63;
    const float* gr = g_gate + (size_t)row*192;
    float P = gr[co] + b1[co];
    float Q = gr[64 + co] + b2[co];
    float R = gr[128 + co] + b3[co];
    float s = 1.f/(1.f + expf(-Q));
    float o = P*s + R;
    g_T2[idx] = o > 0.f ? o : 0.f;
}

// ============================================================
// K6: BN partial sums  grid(50,16), then finalize
// ============================================================
__global__ void k_bnpart()
{
    int n = blockIdx.x, ch = blockIdx.y;
    int tid = threadIdx.x;                       // 128
    float s = 0.f, s2 = 0.f;
    for (int i = tid; i < 72*64; i += 128) {
        int row = ch*72 + (i >> 6);              // row = b*36+t
        int co = i & 63;
        float v = g_T2[((size_t)row*N_ + n)*CO_ + co];
        s += v; s2 += v*v;
    }
    __shared__ float red[256];
    red[tid] = s; red[128 + tid] = s2;
    __syncthreads();
    for (int st = 64; st > 0; st >>= 1) {
        if (tid < st) { red[tid] += red[tid+st]; red[128+tid] += red[128+tid+st]; }
        __syncthreads();
    }
    if (tid == 0) {
        g_bnpart[(n*16 + ch)*2]     = red[0];
        g_bnpart[(n*16 + ch)*2 + 1] = red[128];
    }
}

__global__ void k_bnfin(const float* __restrict__ gamma, const float* __restrict__ beta)
{
    int n = threadIdx.x;
    if (n >= N_) return;
    float s = 0.f, s2 = 0.f;
    for (int ch = 0; ch < 16; ch++) {
        s  += g_bnpart[(n*16 + ch)*2];
        s2 += g_bnpart[(n*16 + ch)*2 + 1];
    }
    const float TOT = (float)(B_*T2T*CO_);
    float mean = s / TOT;
    float var  = s2 / TOT - mean*mean;
    float rstd = rsqrtf(var + 1e-5f);
    float sc = gamma[n]*rstd;
    g_scale[n] = sc;
    g_shift[n] = beta[n] - mean*sc;
}

// ============================================================
// K7: build V[b][k][j]  (BN applied; conv3 windows collapsed)
// ============================================================
__global__ void k_vprep()
{
    int b = blockIdx.x;
    int j = blockIdx.y*256 + threadIdx.x;
    if (j >= J_) return;
    int n = j / CO_;
    float sc = g_scale[n], sh = g_shift[n];
    const float* base = g_T2 + (size_t)b*T2T*J_ + j;
    float TS = 0.f, v0 = 0.f, v1 = 0.f, v34 = 0.f, v35 = 0.f;
    for (int t = 0; t < T2T; t++) {
        float x = base[(size_t)t*J_]*sc + sh;
        TS += x;
        if (t == 0)  v0 = x;
        if (t == 1)  v1 = x;
        if (t == 34) v34 = x;
        if (t == 35) v35 = x;
    }
    g_V[((size_t)b*3 + 0)*J_ + j] = TS - v34 - v35;
    g_V[((size_t)b*3 + 1)*J_ + j] = TS - v0  - v35;
    g_V[((size_t)b*3 + 2)*J_ + j] = TS - v0  - v1;
}

// ============================================================
// K8: pooled[b,o] = c3b[o] + (1/34)*dot(conv3_w[o], V[b])
// ============================================================
__global__ void k_pooled(const float* __restrict__ c3w, const float* __restrict__ c3b)
{
    int o = blockIdx.x;
    int b = blockIdx.y;
    int tid = threadIdx.x;
    const float* w = c3w + (size_t)o*3*J_;
    const float* v = g_V + (size_t)b*3*J_;
    float s = 0.f;
    for (int i = tid; i < 3*J_; i += 256) s += w[i]*v[i];
    __shared__ float red[256];
    red[tid] = s; __syncthreads();
    for (int st = 128; st > 0; st >>= 1) {
        if (tid < st) red[tid] += red[tid+st];
        __syncthreads();
    }
    if (tid == 0) g_pooled[b*OC3 + o] = c3b[o] + red[0]*(1.f/34.f);
}

// ============================================================
// K9: out[b,j] = f1_b[j] + sum_o pooled[b,o]*f1_w[o,j]
// ============================================================
__global__ void k_fc(const float* __restrict__ f1w, const float* __restrict__ f1b,
                     float* __restrict__ out)
{
    int b = blockIdx.y;
    int j = blockIdx.x*128 + threadIdx.x;
    __shared__ float ps[OC3];
    ps[threadIdx.x] = g_pooled[b*OC3 + threadIdx.x];
    __syncthreads();
    float s = f1b[j];
#pragma unroll 4
    for (int o = 0; o < OC3; o++) s += ps[o]*f1w[(size_t)o*J_ + j];
    out[(size_t)b*J_ + j] = s;
}

// ============================================================
// host launcher
// ============================================================
extern "C" void kernel_launch(void* const* d_in, const int* in_sizes, int n_in,
                              void* d_out, int out_size)
{
    const float *X=0,*w11=0,*b11=0,*w12=0,*b12=0,*w13=0,*b13=0;
    const float *chw=0,*chb=0;
    const float *w21=0,*b21=0,*w22=0,*b22=0,*w23=0,*b23=0;
    const float *gamma=0,*beta=0,*c3w=0,*c3b=0,*f1w=0,*f1b=0;
    const int *ei=0;
    int c768=0, c128=0, c24576=0, c64=0, c50=0;
    for (int i = 0; i < n_in; i++) {
        int s = in_sizes[i];
        const void* p = d_in[i];
        switch (s) {
            case 128000:  X = (const float*)p; break;
            case 2048000: ei = (const int*)p; break;
            case 768:
                if (c768==0) w11=(const float*)p; else if (c768==1) w12=(const float*)p; else w13=(const float*)p;
                c768++; break;
            case 128:
                if (c128==0) b11=(const float*)p; else if (c128==1) b12=(const float*)p;
                else if (c128==2) b13=(const float*)p; else if (c128==3) chb=(const float*)p;
                else c3b=(const float*)p;
                c128++; break;
            case 49152:   chw = (const float*)p; break;
            case 24576:
                if (c24576==0) w21=(const float*)p; else if (c24576==1) w22=(const float*)p; else w23=(const float*)p;
                c24576++; break;
            case 64:
                if (c64==0) b21=(const float*)p; else if (c64==1) b22=(const float*)p; else b23=(const float*)p;
                c64++; break;
            case 50:
                if (c50==0) gamma=(const float*)p; else beta=(const float*)p;
                c50++; break;
            case 1228800: c3w = (const float*)p; break;
            case 409600:  f1w = (const float*)p; break;
            case 3200:    f1b = (const float*)p; break;
            default: break;
        }
    }
    float* out = (float*)d_out;

    static const int PROP_SMEM = (2500 + 6400 + 6400 + 64 + 64) * 4;
    cudaFuncSetAttribute(k_cheb_prop, cudaFuncAttributeMaxDynamicSharedMemorySize, PROP_SMEM);

    k_tconv1   <<<B_*N_, 128>>>(X, w11, b11, w12, b12, w13, b13);
    k_prepW    <<<(384*64 + 255)/256, 256>>>(w21, w22, w23);
    k_cheb_prop<<<NG, 256, PROP_SMEM>>>(ei);
    k_gemm<0>  <<<dim3(M_CH/128, 2), 256>>>(chw, chb);
    k_gemm<1>  <<<dim3(M_TC/128, 3), 256>>>(nullptr, nullptr);
    k_tc2epi   <<<(M_TC*CO_ + 255)/256, 256>>>(b21, b22, b23);
    k_bnpart   <<<dim3(N_, 16), 128>>>();
    k_bnfin    <<<1, 64>>>(gamma, beta);
    k_vprep    <<<dim3(B_, (J_+255)/256), 256>>>();
    k_pooled   <<<dim3(OC3, B_), 256>>>(c3w, c3b);
    k_fc       <<<dim3(J_/128, B_), 128>>>(f1w, f1b, out);
}

// round 5
// speedup vs baseline: 2.9481x; 1.3865x over previous
#include <cuda_runtime.h>
#include <cuda_bf16.h>
#include <math.h>
#include <stdint.h>

// ---------------- problem constants ----------------
#define B_   32
#define TW   40
#define N_   50
#define CIN  2
#define H_   128
#define CO_  64
#define E_   800
#define T1   38            // after tconv1
#define T2T  36            // after tconv2
#define NG   (B_*T1)       // 1216 graphs
#define J_   (N_*CO_)      // 3200
#define OC3  128           // conv3 out channels
#define M_CH (NG*N_)       // 60800 rows, cheb GEMM
#define M_TC (B_*T2T*N_)   // 57600 rows, tconv2 GEMM
#define NH_  (N_*H_)       // 6400

// ---------------- scratch (static device, no allocation) ----------------
__device__ float g_T0[NG*NH_];              // 7.78M  (tf32-rounded)
__device__ float g_TX[NG*2*NH_];            // 15.6M  [g][k-1][n][f] (tf32-rounded)
__device__ float g_G [NG*NH_];              // 7.78M  (tf32-rounded)
__device__ float g_Wch[384*128];            // rounded cheb weights
__device__ float g_Wt2[384*192];            // packed+rounded tconv2 weights
__device__ float g_gate[(size_t)M_TC*192];  // 11.06M
__device__ float g_T2[(size_t)M_TC*CO_];    // 3.69M
__device__ float g_V [B_*3*J_];
__device__ float g_bnpart[N_*16*2];
__device__ float g_scale[N_], g_shift[N_];
__device__ float g_pooled[B_*OC3];

// ---------------- helpers ----------------
__device__ __forceinline__ uint32_t f2tf(float f) {
    uint32_t u; asm("cvt.rna.tf32.f32 %0, %1;" : "=r"(u) : "f"(f)); return u;
}
__device__ __forceinline__ float rtf(float f) { return __uint_as_float(f2tf(f)); }
__device__ __forceinline__ void mma_tf32(float* c, const uint32_t* a, const uint32_t* b) {
    asm volatile("mma.sync.aligned.m16n8k8.row.col.f32.tf32.tf32.f32 "
        "{%0,%1,%2,%3}, {%4,%5,%6,%7}, {%8,%9}, {%0,%1,%2,%3};"
        : "+f"(c[0]), "+f"(c[1]), "+f"(c[2]), "+f"(c[3])
        : "r"(a[0]), "r"(a[1]), "r"(a[2]), "r"(a[3]), "r"(b[0]), "r"(b[1]));
}
__device__ __forceinline__ void cp16(uint32_t dst, const void* src) {
    asm volatile("cp.async.cg.shared.global [%0], [%1], 16;" :: "r"(dst), "l"(src));
}

// ============================================================
// K1: tconv1  X(B,40,50,2) -> T0(B,38,50,128), tf32-rounded store
// ============================================================
__global__ void k_tconv1(const float* __restrict__ X,
                         const float* __restrict__ w1, const float* __restrict__ b1,
                         const float* __restrict__ w2, const float* __restrict__ b2,
                         const float* __restrict__ w3, const float* __restrict__ b3)
{
    int bn = blockIdx.x;
    int b = bn / N_, n = bn % N_;
    int h = threadIdx.x;

    __shared__ float xs[TW*CIN];
    for (int i = threadIdx.x; i < TW*CIN; i += blockDim.x) {
        int t = i >> 1, c = i & 1;
        xs[i] = X[((b*TW + t)*N_ + n)*CIN + c];
    }
    float W1[6], W2[6], W3[6];
#pragma unroll
    for (int q = 0; q < 6; q++) {
        W1[q] = w1[q*H_ + h]; W2[q] = w2[q*H_ + h]; W3[q] = w3[q*H_ + h];
    }
    float B1 = b1[h], B2 = b2[h], B3 = b3[h];
    __syncthreads();

    for (int t = 0; t < T1; t++) {
        float P = B1, Q = B2, R = B3;
#pragma unroll
        for (int k = 0; k < 3; k++)
#pragma unroll
            for (int c = 0; c < 2; c++) {
                float v = xs[(t+k)*2 + c];
                int q = k*2 + c;
                P += v*W1[q]; Q += v*W2[q]; R += v*W3[q];
            }
        float s = 1.f/(1.f + expf(-Q));
        float o = P*s + R;
        o = o > 0.f ? o : 0.f;
        g_T0[((size_t)(b*T1 + t)*N_ + n)*H_ + h] = rtf(o);
    }
}

// ============================================================
// K2: Chebyshev propagation -> g_TX[g][{0:t1,1:t2}][n][f]
// register-blocked: one xv load serves 7 output rows
// smem floats: A[2800] | x0[6400] | t1[6400] | dis[64] | deg[64]
// ============================================================
__global__ void k_cheb_prop(const int* __restrict__ EI)
{
    extern __shared__ float sm[];
    float* A   = sm;              // 56x50 padded
    float* x0  = sm + 2800;
    float* t1s = x0 + NH_;
    float* dis = t1s + NH_;
    int*   deg = (int*)(dis + 64);

    int g = blockIdx.x;
    int b = g / T1, t = g % T1;
    int tid = threadIdx.x;               // 256

    for (int i = tid; i < 2800; i += 256) A[i] = 0.f;
    if (tid < N_) deg[tid] = 0;
    __syncthreads();

    const int* rows = EI + ((size_t)(b*TW + t)*2 + 0)*E_;
    const int* cols = EI + ((size_t)(b*TW + t)*2 + 1)*E_;
    for (int e = tid; e < E_; e += 256) atomicAdd(&deg[rows[e]], 1);
    __syncthreads();
    if (tid < N_) { int d = deg[tid]; dis[tid] = d > 0 ? rsqrtf((float)d) : 0.f; }
    __syncthreads();
    for (int e = tid; e < E_; e += 256) {
        int r = rows[e], c = cols[e];
        atomicAdd(&A[r*N_ + c], -dis[r]*dis[c]);
    }
    // load x0 = T0[g] (50x128)
    {
        const float4* src = (const float4*)(g_T0 + (size_t)g*NH_);
        float4* dst = (float4*)x0;
        for (int i = tid; i < NH_/4; i += 256) dst[i] = src[i];
    }
    __syncthreads();

    const int tx = tid & 31;   // float4 column group
    const int ng = tid >> 5;   // 0..7

    // ---- t1 = A @ x0 ----
    {
        float4 acc[7];
#pragma unroll
        for (int i = 0; i < 7; i++) acc[i] = make_float4(0,0,0,0);
        for (int m = 0; m < N_; m++) {
            float4 xv = *(const float4*)(x0 + m*H_ + tx*4);
#pragma unroll
            for (int i = 0; i < 7; i++) {
                float a = A[(ng + 8*i)*N_ + m];   // padded rows are zero
                acc[i].x += a*xv.x; acc[i].y += a*xv.y;
                acc[i].z += a*xv.z; acc[i].w += a*xv.w;
            }
        }
#pragma unroll
        for (int i = 0; i < 7; i++) {
            int n = ng + 8*i;
            if (n < N_) {
                *(float4*)(t1s + n*H_ + tx*4) = acc[i];
                float4 r = make_float4(rtf(acc[i].x), rtf(acc[i].y), rtf(acc[i].z), rtf(acc[i].w));
                *(float4*)(g_TX + (size_t)g*2*NH_ + n*H_ + tx*4) = r;
            }
        }
    }
    __syncthreads();

    // ---- t2 = 2*A@t1 - x0 ----
    {
        float4 acc[7];
#pragma unroll
        for (int i = 0; i < 7; i++) acc[i] = make_float4(0,0,0,0);
        for (int m = 0; m < N_; m++) {
            float4 xv = *(const float4*)(t1s + m*H_ + tx*4);
#pragma unroll
            for (int i = 0; i < 7; i++) {
                float a = A[(ng + 8*i)*N_ + m];
                acc[i].x += a*xv.x; acc[i].y += a*xv.y;
                acc[i].z += a*xv.z; acc[i].w += a*xv.w;
            }
        }
#pragma unroll
        for (int i = 0; i < 7; i++) {
            int n = ng + 8*i;
            if (n < N_) {
                float4 xo = *(const float4*)(x0 + n*H_ + tx*4);
                float4 r;
                r.x = rtf(2.f*acc[i].x - xo.x); r.y = rtf(2.f*acc[i].y - xo.y);
                r.z = rtf(2.f*acc[i].z - xo.z); r.w = rtf(2.f*acc[i].w - xo.w);
                *(float4*)(g_TX + (size_t)g*2*NH_ + NH_ + n*H_ + tx*4) = r;
            }
        }
    }
}

// ============================================================
// K3a: pack+round tconv2 weights.  K3b: round cheb weights.
// ============================================================
__global__ void k_prepW(const float* __restrict__ w1, const float* __restrict__ w2,
                        const float* __restrict__ w3)
{
    int i = blockIdx.x*256 + threadIdx.x;   // over 384*64
    if (i < 384*64) {
        int kt = i >> 6, co = i & 63;
        g_Wt2[kt*192 + co]       = rtf(w1[i]);
        g_Wt2[kt*192 + 64 + co]  = rtf(w2[i]);
        g_Wt2[kt*192 + 128 + co] = rtf(w3[i]);
    }
}
__global__ void k_cvtCh(const float* __restrict__ chw)
{
    int i = blockIdx.x*256 + threadIdx.x;
    if (i < 384*128) g_Wch[i] = rtf(chw[i]);
}

// ============================================================
// K4: tf32 MMA GEMM, cp.async double-buffered.
// BM=128, BN=64, BK=32, 256 threads (8 warps 4x2)
// MODE 0: A = [T0 | TX] (M_CH x 384), B = g_Wch (384x128), bias+relu -> g_G (rounded)
// MODE 1: A = g_G taps (M_TC x 384),  B = g_Wt2 (384x192), raw -> g_gate
// ============================================================
#define AST 36
#define BST 72
#define NKI 12

#define ISSUE_LOADS(ST, K0) do {                                              \
    int kk_ = (K0) >> 7, fb_ = (K0) & 127;                                    \
    _Pragma("unroll")                                                         \
    for (int j_ = 0; j_ < 4; j_++) {                                          \
        const float* s_;                                                      \
        if (MODE == 0)                                                        \
            s_ = (kk_ == 0) ? (g_T0 + ab0[j_] + fb_ + ac4)                    \
                            : (g_TX + abX[j_] + (size_t)(kk_-1)*NH_ + fb_ + ac4); \
        else                                                                  \
            s_ = g_G + ab0[j_] + (size_t)kk_*NH_ + fb_ + ac4;                 \
        cp16((uint32_t)__cvta_generic_to_shared(&As[ST][arow + j_*32][ac4]), s_); \
    }                                                                         \
    _Pragma("unroll")                                                         \
    for (int j_ = 0; j_ < 2; j_++) {                                          \
        int row_ = brow + j_*16;                                              \
        cp16((uint32_t)__cvta_generic_to_shared(&Bs[ST][row_][bc4]),          \
             Bmat + (size_t)((K0) + row_)*BNS + nb + bc4);                    \
    }                                                                         \
    asm volatile("cp.async.commit_group;");                                   \
} while (0)

template<int MODE>
__global__ __launch_bounds__(256) void k_gemm(const float* __restrict__ bias)
{
    __shared__ float As[2][128][AST];
    __shared__ float Bs[2][32][BST];

    const int tid  = threadIdx.x;
    const int bm   = blockIdx.x;
    const int nb   = blockIdx.y * 64;
    const int warp = tid >> 5, lane = tid & 31;
    const int wm = (warp & 3) * 32, wn = (warp >> 2) * 32;
    const int g4 = lane >> 2, tg = lane & 3;

    const int BNS = (MODE == 0) ? 128 : 192;
    const float* Bmat = (MODE == 0) ? g_Wch : g_Wt2;

    const int arow = tid >> 3, ac4 = (tid & 7) << 2;
    const int brow = tid >> 4, bc4 = (tid & 15) << 2;

    size_t ab0[4], abX[4];
#pragma unroll
    for (int j = 0; j < 4; j++) {
        int R = bm*128 + arow + j*32;
        if (MODE == 0) {
            int g = R / N_, n = R - g*N_;
            ab0[j] = (size_t)g*NH_ + (size_t)n*H_;
            abX[j] = (size_t)g*2*NH_ + (size_t)n*H_;
        } else {
            int b = R / (T2T*N_);
            int rem = R - b*(T2T*N_);
            int t = rem / N_, n = rem - t*N_;
            ab0[j] = ((size_t)(b*T1 + t)*N_ + n)*H_;
            abX[j] = 0;
        }
    }

    float acc[2][4][4];
#pragma unroll
    for (int mt = 0; mt < 2; mt++)
#pragma unroll
        for (int nt = 0; nt < 4; nt++)
#pragma unroll
            for (int q = 0; q < 4; q++) acc[mt][nt][q] = 0.f;

    ISSUE_LOADS(0, 0);

    for (int it = 0; it < NKI; it++) {
        const int st = it & 1;
        if (it + 1 < NKI) {
            ISSUE_LOADS(st ^ 1, (it + 1) * 32);
            asm volatile("cp.async.wait_group 1;");
        } else {
            asm volatile("cp.async.wait_group 0;");
        }
        __syncthreads();

#pragma unroll
        for (int kt = 0; kt < 32; kt += 8) {
            uint32_t af[2][4], bf[4][2];
#pragma unroll
            for (int mt = 0; mt < 2; mt++) {
                int m = wm + mt*16;
                af[mt][0] = __float_as_uint(As[st][m + g4    ][kt + tg]);
                af[mt][1] = __float_as_uint(As[st][m + g4 + 8][kt + tg]);
                af[mt][2] = __float_as_uint(As[st][m + g4    ][kt + tg + 4]);
                af[mt][3] = __float_as_uint(As[st][m + g4 + 8][kt + tg + 4]);
            }
#pragma unroll
            for (int nt = 0; nt < 4; nt++) {
                bf[nt][0] = __float_as_uint(Bs[st][kt + tg    ][wn + nt*8 + g4]);
                bf[nt][1] = __float_as_uint(Bs[st][kt + tg + 4][wn + nt*8 + g4]);
            }
#pragma unroll
            for (int mt = 0; mt < 2; mt++)
#pragma unroll
                for (int nt = 0; nt < 4; nt++)
                    mma_tf32(acc[mt][nt], af[mt], bf[nt]);
        }
        __syncthreads();
    }

    // epilogue
#pragma unroll
    for (int mt = 0; mt < 2; mt++) {
        int r0 = bm*128 + wm + mt*16 + g4;
#pragma unroll
        for (int nt = 0; nt < 4; nt++) {
            int c = nb + wn + nt*8 + tg*2;
            float v0 = acc[mt][nt][0], v1 = acc[mt][nt][1];
            float v2 = acc[mt][nt][2], v3 = acc[mt][nt][3];
            if (MODE == 0) {
                float bx = bias[c], by = bias[c+1];
                v0 += bx; v1 += by; v2 += bx; v3 += by;
                v0 = v0 > 0.f ? rtf(v0) : 0.f; v1 = v1 > 0.f ? rtf(v1) : 0.f;
                v2 = v2 > 0.f ? rtf(v2) : 0.f; v3 = v3 > 0.f ? rtf(v3) : 0.f;
                *(float2*)(g_G + (size_t)r0*128 + c)      = make_float2(v0, v1);
                *(float2*)(g_G + (size_t)(r0+8)*128 + c)  = make_float2(v2, v3);
            } else {
                *(float2*)(g_gate + (size_t)r0*192 + c)     = make_float2(v0, v1);
                *(float2*)(g_gate + (size_t)(r0+8)*192 + c) = make_float2(v2, v3);
            }
        }
    }
}

// ============================================================
// K5: tconv2 gate epilogue: relu(P*sig(Q)+R) -> g_T2
// ============================================================
__global__ void k_tc2epi(const float* __restrict__ b1, const float* __restrict__ b2,
                         const float* __restrict__ b3)
{
    int idx = blockIdx.x*256 + threadIdx.x;      // over M_TC*64
    if (idx >= M_TC*CO_) return;
    int row = idx >> 6, co = idx & 63;
    const float* gr = g_gate + (size_t)row*192;
    float P = gr[co] + b1[co];
    float Q = gr[64 + co] + b2[co];
    float R = gr[128 + co] + b3[co];
    float s = 1.f/(1.f + expf(-Q));
    float o = P*s + R;
    g_T2[idx] = o > 0.f ? o : 0.f;
}

// ============================================================
// K6: BN partial sums  grid(50,16), then finalize
// ============================================================
__global__ void k_bnpart()
{
    int n = blockIdx.x, ch = blockIdx.y;
    int tid = threadIdx.x;                       // 128
    float s = 0.f, s2 = 0.f;
    for (int i = tid; i < 72*64; i += 128) {
        int row = ch*72 + (i >> 6);
        int co = i & 63;
        float v = g_T2[((size_t)row*N_ + n)*CO_ + co];
        s += v; s2 += v*v;
    }
    __shared__ float red[256];
    red[tid] = s; red[128 + tid] = s2;
    __syncthreads();
    for (int st = 64; st > 0; st >>= 1) {
        if (tid < st) { red[tid] += red[tid+st]; red[128+tid] += red[128+tid+st]; }
        __syncthreads();
    }
    if (tid == 0) {
        g_bnpart[(n*16 + ch)*2]     = red[0];
        g_bnpart[(n*16 + ch)*2 + 1] = red[128];
    }
}

__global__ void k_bnfin(const float* __restrict__ gamma, const float* __restrict__ beta)
{
    int n = threadIdx.x;
    if (n >= N_) return;
    float s = 0.f, s2 = 0.f;
    for (int ch = 0; ch < 16; ch++) {
        s  += g_bnpart[(n*16 + ch)*2];
        s2 += g_bnpart[(n*16 + ch)*2 + 1];
    }
    const float TOT = (float)(B_*T2T*CO_);
    float mean = s / TOT;
    float var  = s2 / TOT - mean*mean;
    float rstd = rsqrtf(var + 1e-5f);
    float sc = gamma[n]*rstd;
    g_scale[n] = sc;
    g_shift[n] = beta[n] - mean*sc;
}

// ============================================================
// K7: build V[b][k][j]
// ============================================================
__global__ void k_vprep()
{
    int b = blockIdx.x;
    int j = blockIdx.y*256 + threadIdx.x;
    if (j >= J_) return;
    int n = j / CO_;
    float sc = g_scale[n], sh = g_shift[n];
    const float* base = g_T2 + (size_t)b*T2T*J_ + j;
    float TS = 0.f, v0 = 0.f, v1 = 0.f, v34 = 0.f, v35 = 0.f;
    for (int t = 0; t < T2T; t++) {
        float x = base[(size_t)t*J_]*sc + sh;
        TS += x;
        if (t == 0)  v0 = x;
        if (t == 1)  v1 = x;
        if (t == 34) v34 = x;
        if (t == 35) v35 = x;
    }
    g_V[((size_t)b*3 + 0)*J_ + j] = TS - v34 - v35;
    g_V[((size_t)b*3 + 1)*J_ + j] = TS - v0  - v35;
    g_V[((size_t)b*3 + 2)*J_ + j] = TS - v0  - v1;
}

// ============================================================
// K8: pooled[b,o] = c3b[o] + (1/34)*dot(conv3_w[o], V[b])
// ============================================================
__global__ void k_pooled(const float* __restrict__ c3w, const float* __restrict__ c3b)
{
    int o = blockIdx.x;
    int b = blockIdx.y;
    int tid = threadIdx.x;
    const float* w = c3w + (size_t)o*3*J_;
    const float* v = g_V + (size_t)b*3*J_;
    float s = 0.f;
    for (int i = tid; i < 3*J_; i += 256) s += w[i]*v[i];
    __shared__ float red[256];
    red[tid] = s; __syncthreads();
    for (int st = 128; st > 0; st >>= 1) {
        if (tid < st) red[tid] += red[tid+st];
        __syncthreads();
    }
    if (tid == 0) g_pooled[b*OC3 + o] = c3b[o] + red[0]*(1.f/34.f);
}

// ============================================================
// K9: out[b,j] = f1_b[j] + sum_o pooled[b,o]*f1_w[o,j]
// ============================================================
__global__ void k_fc(const float* __restrict__ f1w, const float* __restrict__ f1b,
                     float* __restrict__ out)
{
    int b = blockIdx.y;
    int j = blockIdx.x*128 + threadIdx.x;
    __shared__ float ps[OC3];
    ps[threadIdx.x] = g_pooled[b*OC3 + threadIdx.x];
    __syncthreads();
    float s = f1b[j];
#pragma unroll 4
    for (int o = 0; o < OC3; o++) s += ps[o]*f1w[(size_t)o*J_ + j];
    out[(size_t)b*J_ + j] = s;
}

// ============================================================
// host launcher
// ============================================================
extern "C" void kernel_launch(void* const* d_in, const int* in_sizes, int n_in,
                              void* d_out, int out_size)
{
    const float *X=0,*w11=0,*b11=0,*w12=0,*b12=0,*w13=0,*b13=0;
    const float *chw=0,*chb=0;
    const float *w21=0,*b21=0,*w22=0,*b22=0,*w23=0,*b23=0;
    const float *gamma=0,*beta=0,*c3w=0,*c3b=0,*f1w=0,*f1b=0;
    const int *ei=0;
    int c768=0, c128=0, c24576=0, c64=0, c50=0;
    for (int i = 0; i < n_in; i++) {
        int s = in_sizes[i];
        const void* p = d_in[i];
        switch (s) {
            case 128000:  X = (const float*)p; break;
            case 2048000: ei = (const int*)p; break;
            case 768:
                if (c768==0) w11=(const float*)p; else if (c768==1) w12=(const float*)p; else w13=(const float*)p;
                c768++; break;
            case 128:
                if (c128==0) b11=(const float*)p; else if (c128==1) b12=(const float*)p;
                else if (c128==2) b13=(const float*)p; else if (c128==3) chb=(const float*)p;
                else c3b=(const float*)p;
                c128++; break;
            case 49152:   chw = (const float*)p; break;
            case 24576:
                if (c24576==0) w21=(const float*)p; else if (c24576==1) w22=(const float*)p; else w23=(const float*)p;
                c24576++; break;
            case 64:
                if (c64==0) b21=(const float*)p; else if (c64==1) b22=(const float*)p; else b23=(const float*)p;
                c64++; break;
            case 50:
                if (c50==0) gamma=(const float*)p; else beta=(const float*)p;
                c50++; break;
            case 1228800: c3w = (const float*)p; break;
            case 409600:  f1w = (const float*)p; break;
            case 3200:    f1b = (const float*)p; break;
            default: break;
        }
    }
    float* out = (float*)d_out;

    static const int PROP_SMEM = (2800 + NH_ + NH_ + 64 + 64) * 4;
    cudaFuncSetAttribute(k_cheb_prop, cudaFuncAttributeMaxDynamicSharedMemorySize, PROP_SMEM);

    k_tconv1   <<<B_*N_, 128>>>(X, w11, b11, w12, b12, w13, b13);
    k_prepW    <<<(384*64 + 255)/256, 256>>>(w21, w22, w23);
    k_cvtCh    <<<(384*128 + 255)/256, 256>>>(chw);
    k_cheb_prop<<<NG, 256, PROP_SMEM>>>(ei);
    k_gemm<0>  <<<dim3(M_CH/128, 2), 256>>>(chb);
    k_gemm<1>  <<<dim3(M_TC/128, 3), 256>>>(nullptr);
    k_tc2epi   <<<(M_TC*CO_ + 255)/256, 256>>>(b21, b22, b23);
    k_bnpart   <<<dim3(N_, 16), 128>>>();
    k_bnfin    <<<1, 64>>>(gamma, beta);
    k_vprep    <<<dim3(B_, (J_+255)/256), 256>>>();
    k_pooled   <<<dim3(OC3, B_), 256>>>(c3w, c3b);
    k_fc       <<<dim3(J_/128, B_), 128>>>(f1w, f1b, out);
}